// round 2
// baseline (speedup 1.0000x reference)
#include <cuda_runtime.h>
#include <math.h>

#define FEAT 256
#define EMB 512
#define NPTS 32
#define SDIM 16
#define MAX_E 4096
#define MAX_NODES 10000
#define EPS 0.1f
#define INV_EPS 10.0f
#define MAX_ITER 10
#define THRESH 0.1f
#define PPB 4   // pairs (warps) per block in sinkhorn kernels

// ---------------- scratch (static device globals; no allocs) ----------------
__device__ float  g_z[MAX_NODES * EMB];                         // 20.5 MB
__device__ float  g_C[2 * MAX_E * NPTS * NPTS];                 // 33.5 MB
__device__ float  g_uv[(size_t)2 * MAX_E * MAX_ITER * 2 * NPTS];// 21.0 MB
__device__ float  g_err[2 * MAX_ITER];
__device__ int    g_T[2];
__device__ double g_acc[2];

// ---------------- GEMM: z = x @ W  (M x 256) @ (256 x 512) -----------------
#define BM 128
#define BN 64
#define BK 16
__global__ __launch_bounds__(256) void sge_gemm_kernel(
    const float* __restrict__ A, const float* __restrict__ B, int M)
{
    __shared__ float As[BK][BM + 4];   // transposed A tile, padded
    __shared__ float Bs[BK][BN];
    const int tid = threadIdx.x;
    const int m0 = blockIdx.y * BM;
    const int n0 = blockIdx.x * BN;
    const int arow = tid >> 1;          // 0..127
    const int acol = (tid & 1) * 8;     // 0 or 8
    const int brow = tid >> 4;          // 0..15
    const int bcol = (tid & 15) * 4;    // 0..60
    const int ty = tid >> 4;            // 0..15 (rows of 8)
    const int tx = tid & 15;            // 0..15 (cols of 4)

    float acc[8][4];
#pragma unroll
    for (int i = 0; i < 8; i++)
#pragma unroll
        for (int j = 0; j < 4; j++) acc[i][j] = 0.f;

    for (int k0 = 0; k0 < FEAT; k0 += BK) {
        float4 a0 = make_float4(0.f, 0.f, 0.f, 0.f), a1 = a0;
        if (m0 + arow < M) {
            const float* ap = A + (size_t)(m0 + arow) * FEAT + k0 + acol;
            a0 = *(const float4*)ap;
            a1 = *(const float4*)(ap + 4);
        }
        As[acol + 0][arow] = a0.x; As[acol + 1][arow] = a0.y;
        As[acol + 2][arow] = a0.z; As[acol + 3][arow] = a0.w;
        As[acol + 4][arow] = a1.x; As[acol + 5][arow] = a1.y;
        As[acol + 6][arow] = a1.z; As[acol + 7][arow] = a1.w;
        *(float4*)&Bs[brow][bcol] =
            *(const float4*)(B + (size_t)(k0 + brow) * EMB + n0 + bcol);
        __syncthreads();
#pragma unroll
        for (int k = 0; k < BK; k++) {
            float ar[8], br[4];
            *(float4*)&ar[0] = *(const float4*)&As[k][ty * 8];
            *(float4*)&ar[4] = *(const float4*)&As[k][ty * 8 + 4];
            *(float4*)&br[0] = *(const float4*)&Bs[k][tx * 4];
#pragma unroll
            for (int i = 0; i < 8; i++)
#pragma unroll
                for (int j = 0; j < 4; j++)
                    acc[i][j] = fmaf(ar[i], br[j], acc[i][j]);
        }
        __syncthreads();
    }
#pragma unroll
    for (int i = 0; i < 8; i++) {
        int row = m0 + ty * 8 + i;
        if (row < M) {
            *(float4*)&g_z[(size_t)row * EMB + n0 + tx * 4] =
                make_float4(acc[i][0], acc[i][1], acc[i][2], acc[i][3]);
        }
    }
}

// ---------------- init: zero accumulators (must re-run every replay) --------
__global__ void sge_init_kernel()
{
    int t = threadIdx.x;
    if (t < 2 * MAX_ITER) g_err[t] = 0.f;
    if (t < 2) g_acc[t] = 0.0;
}

// ---------------- pass 1: C + 10 Sinkhorn iterations, snapshots + err -------
__global__ __launch_bounds__(128) void sge_sinkhorn_pass1(
    const int* __restrict__ ep, const int* __restrict__ en, int E)
{
    __shared__ float Csh[PPB][NPTS][NPTS + 1];
    __shared__ float bsh[PPB][NPTS][SDIM];
    __shared__ float vsh[PPB][NPTS];
    __shared__ float ush[PPB][NPTS];
    const int warp = threadIdx.x >> 5, lane = threadIdx.x & 31;
    const int p = blockIdx.x * PPB + warp;
    if (p >= 2 * E) return;
    const int batch = (p >= E) ? 1 : 0;
    const int e = p - batch * E;
    const int* edges = batch ? en : ep;
    const int nx = edges[e];
    const int ny = edges[E + e];

    // gather point clouds: lane = point index; a in regs, b in smem
    float a[SDIM];
    {
        const float4* ap = (const float4*)(g_z + (size_t)nx * EMB + lane * SDIM);
        const float4* bp = (const float4*)(g_z + (size_t)ny * EMB + lane * SDIM);
#pragma unroll
        for (int q = 0; q < 4; q++) {
            float4 v4 = ap[q];
            a[q * 4 + 0] = v4.x; a[q * 4 + 1] = v4.y;
            a[q * 4 + 2] = v4.z; a[q * 4 + 3] = v4.w;
            *(float4*)&bsh[warp][lane][q * 4] = bp[q];
        }
    }
    __syncwarp();

    // cost matrix C[i][j] = ||a_i - b_j||^2
#pragma unroll 4
    for (int j = 0; j < NPTS; j++) {
        float c = 0.f;
#pragma unroll
        for (int d = 0; d < SDIM; d++) {
            float df = a[d] - bsh[warp][j][d];
            c = fmaf(df, df, c);
        }
        Csh[warp][lane][j] = c;
    }
    __syncwarp();
    // persist C (coalesced store, conflict-free column reads via +1 pad)
    float* Cg = g_C + (size_t)p * (NPTS * NPTS);
#pragma unroll
    for (int r = 0; r < NPTS; r++) Cg[r * NPTS + lane] = Csh[warp][r][lane];

    float u = 0.f, v = 0.f;
    const float logmu_eps = EPS * logf(1.0f / NPTS + 1e-8f);
    float* uvp = g_uv + (size_t)p * (MAX_ITER * 2 * NPTS);

    for (int t = 0; t < MAX_ITER; t++) {
        vsh[warp][lane] = v;
        __syncwarp();
        // u-half: u_new_i = eps*log(mu+1e-8) - eps*LSE_j((v_j - C_ij)/eps)
        float m = -1e30f;
#pragma unroll
        for (int j = 0; j < NPTS; j++) {
            float tv = (vsh[warp][j] - Csh[warp][lane][j]) * INV_EPS;
            m = fmaxf(m, tv);
        }
        float s = 0.f;
#pragma unroll
        for (int j = 0; j < NPTS; j++) {
            float tv = (vsh[warp][j] - Csh[warp][lane][j]) * INV_EPS;
            s += __expf(tv - m);
        }
        float unew = logmu_eps - EPS * (m + __logf(s));
        float du = fabsf(unew - u);
        u = unew;
#pragma unroll
        for (int off = 16; off; off >>= 1)
            du += __shfl_xor_sync(0xffffffffu, du, off);
        ush[warp][lane] = u;
        __syncwarp();
        // v-half (uses u_new): v_j = eps*log(nu+1e-8) - eps*LSE_i((u_i - C_ij)/eps)
        m = -1e30f;
#pragma unroll
        for (int i = 0; i < NPTS; i++) {
            float tv = (ush[warp][i] - Csh[warp][i][lane]) * INV_EPS;
            m = fmaxf(m, tv);
        }
        s = 0.f;
#pragma unroll
        for (int i = 0; i < NPTS; i++) {
            float tv = (ush[warp][i] - Csh[warp][i][lane]) * INV_EPS;
            s += __expf(tv - m);
        }
        v = logmu_eps - EPS * (m + __logf(s));
        // snapshot after this iteration
        uvp[t * 2 * NPTS + lane] = u;
        uvp[t * 2 * NPTS + NPTS + lane] = v;
        if (lane == 0) atomicAdd(&g_err[batch * MAX_ITER + t], du);
        __syncwarp();  // protect vsh/ush for next iteration
    }
}

// ---------------- T: first iteration where batch-mean err < thresh ----------
__global__ void sge_compute_T(int E)
{
    int b = threadIdx.x;
    if (b < 2) {
        int T = MAX_ITER;
        float invE = 1.0f / (float)E;
        for (int t = 0; t < MAX_ITER; t++) {
            if (g_err[b * MAX_ITER + t] * invE < THRESH) { T = t + 1; break; }
        }
        g_T[b] = T;
    }
}

// ---------------- pass 2: cost = sum(pi*C), accumulate loss terms -----------
__global__ __launch_bounds__(128) void sge_sinkhorn_pass2(int E)
{
    __shared__ float Csh[PPB][NPTS][NPTS + 1];
    __shared__ float vsh[PPB][NPTS];
    const int warp = threadIdx.x >> 5, lane = threadIdx.x & 31;
    const int p = blockIdx.x * PPB + warp;
    if (p >= 2 * E) return;
    const int batch = (p >= E) ? 1 : 0;
    const int T = g_T[batch];
    const float* uvp = g_uv + (size_t)p * (MAX_ITER * 2 * NPTS) + (T - 1) * 2 * NPTS;
    float u = uvp[lane];
    float v = uvp[NPTS + lane];
    vsh[warp][lane] = v;
    const float* Cg = g_C + (size_t)p * (NPTS * NPTS);
#pragma unroll
    for (int r = 0; r < NPTS; r++) Csh[warp][r][lane] = Cg[r * NPTS + lane];
    __syncwarp();
    float cost = 0.f;
#pragma unroll
    for (int j = 0; j < NPTS; j++) {
        float Cij = Csh[warp][lane][j];
        float pi = __expf((u + vsh[warp][j] - Cij) * INV_EPS);
        cost = fmaf(pi, Cij, cost);
    }
#pragma unroll
    for (int off = 16; off; off >>= 1)
        cost += __shfl_xor_sync(0xffffffffu, cost, off);
    if (lane == 0) {
        float energy = -cost;
        double contrib = batch ? (double)__expf(energy)
                               : (double)energy * (double)energy;
        atomicAdd(&g_acc[batch], contrib);
    }
}

// ---------------- finalize ---------------------------------------------------
__global__ void sge_finalize_kernel(float* out, int out_size, int E)
{
    float loss = (float)((g_acc[0] + g_acc[1]) / (double)E);
    for (int i = threadIdx.x; i < out_size; i += blockDim.x) out[i] = loss;
}

// ---------------- launch -----------------------------------------------------
extern "C" void kernel_launch(void* const* d_in, const int* in_sizes, int n_in,
                              void* d_out, int out_size)
{
    const float* x = (const float*)d_in[0];
    const float* W = (const float*)d_in[1];
    const int* ep  = (const int*)d_in[2];
    const int* en  = (const int*)d_in[3];
    int M = in_sizes[0] / FEAT;
    if (M > MAX_NODES) M = MAX_NODES;
    int E = in_sizes[2] / 2;
    if (E > MAX_E) E = MAX_E;

    dim3 ggrid(EMB / BN, (M + BM - 1) / BM);
    sge_gemm_kernel<<<ggrid, 256>>>(x, W, M);
    sge_init_kernel<<<1, 32>>>();
    int nblocks = (2 * E + PPB - 1) / PPB;
    sge_sinkhorn_pass1<<<nblocks, 128>>>(ep, en, E);
    sge_compute_T<<<1, 2>>>(E);
    sge_sinkhorn_pass2<<<nblocks, 128>>>(E);
    sge_finalize_kernel<<<1, 32>>>((float*)d_out, out_size, E);
}

// round 7
// speedup vs baseline: 1.2469x; 1.2469x over previous
#include <cuda_runtime.h>
#include <cuda_bf16.h>
#include <cstdint>
#include <math.h>

#define FEAT 256
#define EMB 512
#define NPTS 32
#define SDIM 16
#define MAX_E 4096
#define MAX_NODES 10000
#define MPAD 10112          // 79 * 128
#define EPS 0.1f
#define INV_EPS 10.0f
#define MAX_ITER 10
#define THRESH 0.1f
#define PPB 4               // pairs (warps) per block in sinkhorn pass1
#define NU_TILDE 0.03125001f   // 1/32 + 1e-8

// ---------------- scratch (static device globals; no allocs) ----------------
__device__ __align__(256) float         g_z[(size_t)MPAD * EMB];        // 20.7 MB
__device__ __align__(256) __nv_bfloat16 g_xhi[(size_t)MPAD * FEAT];
__device__ __align__(256) __nv_bfloat16 g_xlo[(size_t)MPAD * FEAT];
__device__ __align__(256) __nv_bfloat16 g_wthi[(size_t)EMB * FEAT];     // W^T [n][k]
__device__ __align__(256) __nv_bfloat16 g_wtlo[(size_t)EMB * FEAT];
__device__ __align__(256) float         g_cost[2 * MAX_E * MAX_ITER];
__device__ float  g_err[2 * MAX_ITER];
__device__ double g_accd;

// ---------------- convert kernels -------------------------------------------
__global__ __launch_bounds__(256) void sge_convert_x(const float* __restrict__ x, int M)
{
    int idx = blockIdx.x * 256 + threadIdx.x;
    if (idx < 2 * MAX_ITER) g_err[idx] = 0.f;
    if (idx == 2 * MAX_ITER) g_accd = 0.0;
    if (idx >= MPAD * FEAT) return;
    int row = idx / FEAT;
    float v = (row < M) ? x[idx] : 0.f;
    __nv_bfloat16 hi = __float2bfloat16(v);
    __nv_bfloat16 lo = __float2bfloat16(v - __bfloat162float(hi));
    g_xhi[idx] = hi;
    g_xlo[idx] = lo;
}

__global__ __launch_bounds__(256) void sge_convert_w(const float* __restrict__ W)
{
    int idx = blockIdx.x * 256 + threadIdx.x;
    if (idx >= EMB * FEAT) return;
    int n = idx / FEAT, k = idx % FEAT;
    float v = W[(size_t)k * EMB + n];
    __nv_bfloat16 hi = __float2bfloat16(v);
    __nv_bfloat16 lo = __float2bfloat16(v - __bfloat162float(hi));
    g_wthi[idx] = hi;
    g_wtlo[idx] = lo;
}

// ---------------- HMMA GEMM: z = x @ W via bf16 hi/lo split -----------------
// mma.sync.aligned.m16n8k16.row.col.f32.bf16.bf16.f32
__device__ __forceinline__ void mma16816(
    float& c0, float& c1, float& c2, float& c3,
    uint32_t a0, uint32_t a1, uint32_t a2, uint32_t a3,
    uint32_t b0, uint32_t b1)
{
    asm volatile(
        "mma.sync.aligned.m16n8k16.row.col.f32.bf16.bf16.f32 "
        "{%0,%1,%2,%3}, {%4,%5,%6,%7}, {%8,%9}, {%0,%1,%2,%3};\n"
        : "+f"(c0), "+f"(c1), "+f"(c2), "+f"(c3)
        : "r"(a0), "r"(a1), "r"(a2), "r"(a3), "r"(b0), "r"(b1));
}

#define KC 32               // k-chunk
#define ROWP 40             // padded smem row (elements) -> 80B rows, 16B aligned

// tile loader: 128 rows x 32 k bf16 from [row][256] global into [128][ROWP] smem
__device__ __forceinline__ void ld_tile(__nv_bfloat16 (*dst)[ROWP],
    const __nv_bfloat16* __restrict__ g, int row0, int c0, int tid)
{
#pragma unroll
    for (int l = 0; l < 2; l++) {
        int u = l * 256 + tid;          // 0..511 16B-units
        int r = u >> 2, s = u & 3;      // row 0..127, 16B segment 0..3
        const uint4* src = (const uint4*)(g + (size_t)(row0 + r) * FEAT + c0 * KC + s * 8);
        *(uint4*)&dst[r][s * 8] = *src;
    }
}

__global__ __launch_bounds__(256) void sge_gemm_mma(int M)
{
    __shared__ __nv_bfloat16 Ah[128][ROWP];
    __shared__ __nv_bfloat16 Al[128][ROWP];
    __shared__ __nv_bfloat16 Bh[128][ROWP];
    __shared__ __nv_bfloat16 Bl[128][ROWP];

    const int tid = threadIdx.x;
    const int wid = tid >> 5, lane = tid & 31;
    const int g = lane >> 2, t = lane & 3;
    const int wm = wid & 1, wn = wid >> 1;          // warp: 64x32 of the 128x128 tile
    const int M0 = blockIdx.y * 128, N0 = blockIdx.x * 128;
    const int warpM = wm * 64, warpN = wn * 32;

    float acc[4][4][4];                              // [mi][ni][reg]
#pragma unroll
    for (int mi = 0; mi < 4; mi++)
#pragma unroll
        for (int ni = 0; ni < 4; ni++)
#pragma unroll
            for (int r = 0; r < 4; r++) acc[mi][ni][r] = 0.f;

    for (int c = 0; c < FEAT / KC; c++) {
        ld_tile(Ah, g_xhi,  M0, c, tid);
        ld_tile(Al, g_xlo,  M0, c, tid);
        ld_tile(Bh, g_wthi, N0, c, tid);
        ld_tile(Bl, g_wtlo, N0, c, tid);
        __syncthreads();
#pragma unroll
        for (int ks = 0; ks < 2; ks++) {
            const int kb = ks * 16;
            uint32_t bh[4][2], bl[4][2];
#pragma unroll
            for (int ni = 0; ni < 4; ni++) {
                int nr = warpN + ni * 8 + g;
                bh[ni][0] = *(const uint32_t*)&Bh[nr][kb + 2 * t];
                bh[ni][1] = *(const uint32_t*)&Bh[nr][kb + 2 * t + 8];
                bl[ni][0] = *(const uint32_t*)&Bl[nr][kb + 2 * t];
                bl[ni][1] = *(const uint32_t*)&Bl[nr][kb + 2 * t + 8];
            }
            uint32_t af[4][4];
#pragma unroll
            for (int mi = 0; mi < 4; mi++) {
                int mr = warpM + mi * 16;
                af[mi][0] = *(const uint32_t*)&Ah[mr + g][kb + 2 * t];
                af[mi][1] = *(const uint32_t*)&Ah[mr + g + 8][kb + 2 * t];
                af[mi][2] = *(const uint32_t*)&Ah[mr + g][kb + 2 * t + 8];
                af[mi][3] = *(const uint32_t*)&Ah[mr + g + 8][kb + 2 * t + 8];
            }
#pragma unroll
            for (int mi = 0; mi < 4; mi++)
#pragma unroll
                for (int ni = 0; ni < 4; ni++) {
                    mma16816(acc[mi][ni][0], acc[mi][ni][1], acc[mi][ni][2], acc[mi][ni][3],
                             af[mi][0], af[mi][1], af[mi][2], af[mi][3],
                             bh[ni][0], bh[ni][1]);
                    mma16816(acc[mi][ni][0], acc[mi][ni][1], acc[mi][ni][2], acc[mi][ni][3],
                             af[mi][0], af[mi][1], af[mi][2], af[mi][3],
                             bl[ni][0], bl[ni][1]);
                }
#pragma unroll
            for (int mi = 0; mi < 4; mi++) {
                int mr = warpM + mi * 16;
                af[mi][0] = *(const uint32_t*)&Al[mr + g][kb + 2 * t];
                af[mi][1] = *(const uint32_t*)&Al[mr + g + 8][kb + 2 * t];
                af[mi][2] = *(const uint32_t*)&Al[mr + g][kb + 2 * t + 8];
                af[mi][3] = *(const uint32_t*)&Al[mr + g + 8][kb + 2 * t + 8];
            }
#pragma unroll
            for (int mi = 0; mi < 4; mi++)
#pragma unroll
                for (int ni = 0; ni < 4; ni++)
                    mma16816(acc[mi][ni][0], acc[mi][ni][1], acc[mi][ni][2], acc[mi][ni][3],
                             af[mi][0], af[mi][1], af[mi][2], af[mi][3],
                             bh[ni][0], bh[ni][1]);
        }
        __syncthreads();
    }

    // epilogue: c0,c1 -> (row g, cols 2t,2t+1); c2,c3 -> (row g+8)
#pragma unroll
    for (int mi = 0; mi < 4; mi++) {
        int r0 = M0 + warpM + mi * 16 + g;
#pragma unroll
        for (int ni = 0; ni < 4; ni++) {
            int col = N0 + warpN + ni * 8 + 2 * t;
            if (r0 < M)
                *(float2*)&g_z[(size_t)r0 * EMB + col] =
                    make_float2(acc[mi][ni][0], acc[mi][ni][1]);
            if (r0 + 8 < M)
                *(float2*)&g_z[(size_t)(r0 + 8) * EMB + col] =
                    make_float2(acc[mi][ni][2], acc[mi][ni][3]);
        }
    }
}

// ---------------- pass 1: Sinkhorn iterations, per-iter cost + err -----------
__global__ __launch_bounds__(128) void sge_sinkhorn_pass1(
    const int* __restrict__ ep, const int* __restrict__ en, int E)
{
    __shared__ float Csh[PPB][NPTS][NPTS + 1];
    __shared__ float bsh[PPB][NPTS][SDIM];
    __shared__ float vsh[PPB][NPTS];
    __shared__ float ush[PPB][NPTS];
    const int warp = threadIdx.x >> 5, lane = threadIdx.x & 31;
    const int p = blockIdx.x * PPB + warp;
    if (p >= 2 * E) return;
    const int batch = (p >= E) ? 1 : 0;
    const int e = p - batch * E;
    const int* edges = batch ? en : ep;
    const int nx = edges[e];
    const int ny = edges[E + e];

    // gather point clouds: lane = point index; a in regs, b in smem
    float a[SDIM];
    {
        const float4* ap = (const float4*)(g_z + (size_t)nx * EMB + lane * SDIM);
        const float4* bp = (const float4*)(g_z + (size_t)ny * EMB + lane * SDIM);
#pragma unroll
        for (int q = 0; q < 4; q++) {
            float4 v4 = ap[q];
            a[q * 4 + 0] = v4.x; a[q * 4 + 1] = v4.y;
            a[q * 4 + 2] = v4.z; a[q * 4 + 3] = v4.w;
            *(float4*)&bsh[warp][lane][q * 4] = bp[q];
        }
    }
    __syncwarp();

    // C row in registers (row i = lane) + smem copy for column access in v-half
    float Crow[NPTS];
#pragma unroll 8
    for (int j = 0; j < NPTS; j++) {
        float c = 0.f;
#pragma unroll
        for (int d = 0; d < SDIM; d++) {
            float df = a[d] - bsh[warp][j][d];
            c = fmaf(df, df, c);
        }
        Crow[j] = c;
        Csh[warp][lane][j] = c;
    }
    __syncwarp();

    float u = 0.f, v = 0.f;
    const float logmu_eps = EPS * logf(NU_TILDE);

    for (int t = 0; t < MAX_ITER; t++) {
        vsh[warp][lane] = v;
        __syncwarp();
        // u-half: u_i = eps*log(nu~) - eps*LSE_j((v_j - C_ij)/eps)
        float m = -1e30f;
#pragma unroll
        for (int j = 0; j < NPTS; j++)
            m = fmaxf(m, (vsh[warp][j] - Crow[j]) * INV_EPS);
        float s = 0.f;
#pragma unroll
        for (int j = 0; j < NPTS; j++)
            s += __expf((vsh[warp][j] - Crow[j]) * INV_EPS - m);
        float unew = logmu_eps - EPS * (m + __logf(s));
        float du = fabsf(unew - u);
        u = unew;
#pragma unroll
        for (int off = 16; off; off >>= 1)
            du += __shfl_xor_sync(0xffffffffu, du, off);
        ush[warp][lane] = u;
        __syncwarp();
        // v-half (lane = column j), with fused transport-cost accumulation:
        // pi_ij = nu~ * exp(tv_i - m_j)/s_j  where tv_i = (u_i - C_ij)/eps
        float m2 = -1e30f;
#pragma unroll
        for (int i = 0; i < NPTS; i++)
            m2 = fmaxf(m2, (ush[warp][i] - Csh[warp][i][lane]) * INV_EPS);
        float s2 = 0.f, sc = 0.f;
#pragma unroll
        for (int i = 0; i < NPTS; i++) {
            float Ci = Csh[warp][i][lane];
            float e2 = __expf((ush[warp][i] - Ci) * INV_EPS - m2);
            s2 += e2;
            sc = fmaf(e2, Ci, sc);
        }
        v = logmu_eps - EPS * (m2 + __logf(s2));
        float costl = NU_TILDE * sc / s2;   // column j's share of sum(pi*C)
#pragma unroll
        for (int off = 16; off; off >>= 1)
            costl += __shfl_xor_sync(0xffffffffu, costl, off);
        if (lane == 0) {
            g_cost[p * MAX_ITER + t] = costl;
            atomicAdd(&g_err[batch * MAX_ITER + t], du);
        }
        __syncwarp();
    }
}

// ---------------- reduce: pick iteration T-1 cost, accumulate loss -----------
__global__ __launch_bounds__(256) void sge_reduce(int E)
{
    __shared__ double sd[256];
    __shared__ int Tsh[2];
    if (threadIdx.x < 2) {
        int b = threadIdx.x;
        int T = MAX_ITER;
        float invE = 1.0f / (float)E;
        for (int t = 0; t < MAX_ITER; t++)
            if (g_err[b * MAX_ITER + t] * invE < THRESH) { T = t + 1; break; }
        Tsh[b] = T;
    }
    __syncthreads();
    int p = blockIdx.x * 256 + threadIdx.x;
    double con = 0.0;
    if (p < 2 * E) {
        int b = (p >= E) ? 1 : 0;
        float c = g_cost[p * MAX_ITER + Tsh[b] - 1];
        float energy = -c;
        con = b ? (double)__expf(energy) : (double)energy * (double)energy;
    }
    sd[threadIdx.x] = con;
    __syncthreads();
    for (int s2 = 128; s2; s2 >>= 1) {
        if (threadIdx.x < s2) sd[threadIdx.x] += sd[threadIdx.x + s2];
        __syncthreads();
    }
    if (threadIdx.x == 0) atomicAdd(&g_accd, sd[0]);
}

// ---------------- finalize ---------------------------------------------------
__global__ void sge_finalize_kernel(float* out, int out_size, int E)
{
    float loss = (float)(g_accd / (double)E);
    for (int i = threadIdx.x; i < out_size; i += blockDim.x) out[i] = loss;
}

// ---------------- launch -----------------------------------------------------
extern "C" void kernel_launch(void* const* d_in, const int* in_sizes, int n_in,
                              void* d_out, int out_size)
{
    const float* x = (const float*)d_in[0];
    const float* W = (const float*)d_in[1];
    const int* ep  = (const int*)d_in[2];
    const int* en  = (const int*)d_in[3];
    int M = in_sizes[0] / FEAT;
    if (M > MAX_NODES) M = MAX_NODES;
    int E = in_sizes[2] / 2;
    if (E > MAX_E) E = MAX_E;

    sge_convert_x<<<(MPAD * FEAT + 255) / 256, 256>>>(x, M);
    sge_convert_w<<<(EMB * FEAT + 255) / 256, 256>>>(W);
    sge_gemm_mma<<<dim3(EMB / 128, MPAD / 128), 256>>>(M);
    int nblocks = (2 * E + PPB - 1) / PPB;
    sge_sinkhorn_pass1<<<nblocks, 128>>>(ep, en, E);
    sge_reduce<<<(2 * E + 255) / 256, 256>>>(E);
    sge_finalize_kernel<<<1, 32>>>((float*)d_out, out_size, E);
}

// round 8
// speedup vs baseline: 1.2758x; 1.0232x over previous
#include <cuda_runtime.h>
#include <cuda_bf16.h>
#include <cstdint>
#include <math.h>

#define FEAT 256
#define EMB 512
#define NPTS 32
#define SDIM 16
#define MAX_E 4096
#define MAX_NODES 10000
#define MPAD 10112          // 79 * 128
#define EPS 0.1f
#define MAX_ITER 10
#define PPB 4               // pairs (warps) per block in sinkhorn pass1
#define NU_TILDE 0.03125001f          // 1/32 + 1e-8
#define SCALE 14.426950408889634f     // (1/EPS)*log2(e)
#define K2LOG (-4.9999995385f)        // log2(NU_TILDE)
#define THRESH_SCALED 1.4426950408889634f  // 0.1 * SCALE

// ---------------- scratch (static device globals; no allocs) ----------------
__device__ __align__(256) float         g_z[(size_t)MPAD * EMB];
__device__ __align__(256) __nv_bfloat16 g_xhi[(size_t)MPAD * FEAT];
__device__ __align__(256) __nv_bfloat16 g_xlo[(size_t)MPAD * FEAT];
__device__ __align__(256) __nv_bfloat16 g_wthi[(size_t)EMB * FEAT];   // W^T [n][k]
__device__ __align__(256) __nv_bfloat16 g_wtlo[(size_t)EMB * FEAT];
__device__ __align__(256) float         g_cost[2 * MAX_E * MAX_ITER];
__device__ float  g_err[2 * MAX_ITER];
__device__ double g_accd;

// ---------------- fast math wrappers ----------------------------------------
__device__ __forceinline__ float ex2(float x) {
    float y; asm("ex2.approx.ftz.f32 %0, %1;" : "=f"(y) : "f"(x)); return y;
}
__device__ __forceinline__ float lg2(float x) {
    float y; asm("lg2.approx.ftz.f32 %0, %1;" : "=f"(y) : "f"(x)); return y;
}
__device__ __forceinline__ uint32_t smem_u32(const void* p) {
    uint32_t a;
    asm("{ .reg .u64 t; cvta.to.shared.u64 t, %1; cvt.u32.u64 %0, t; }"
        : "=r"(a) : "l"(p));
    return a;
}

// ---------------- convert kernels -------------------------------------------
__global__ __launch_bounds__(256) void sge_convert_x(const float* __restrict__ x, int M)
{
    int idx = blockIdx.x * 256 + threadIdx.x;
    if (idx < 2 * MAX_ITER) g_err[idx] = 0.f;
    if (idx == 2 * MAX_ITER) g_accd = 0.0;
    if (idx >= MPAD * FEAT) return;
    int row = idx / FEAT;
    float v = (row < M) ? x[idx] : 0.f;
    __nv_bfloat16 hi = __float2bfloat16(v);
    __nv_bfloat16 lo = __float2bfloat16(v - __bfloat162float(hi));
    g_xhi[idx] = hi;
    g_xlo[idx] = lo;
}

__global__ __launch_bounds__(256) void sge_convert_w(const float* __restrict__ W)
{
    int idx = blockIdx.x * 256 + threadIdx.x;
    if (idx >= EMB * FEAT) return;
    int n = idx / FEAT, k = idx % FEAT;
    float v = W[(size_t)k * EMB + n];
    __nv_bfloat16 hi = __float2bfloat16(v);
    __nv_bfloat16 lo = __float2bfloat16(v - __bfloat162float(hi));
    g_wthi[idx] = hi;
    g_wtlo[idx] = lo;
}

// ---------------- HMMA GEMM: z = x @ W via bf16 hi/lo split -----------------
__device__ __forceinline__ void mma16816(
    float& c0, float& c1, float& c2, float& c3,
    uint32_t a0, uint32_t a1, uint32_t a2, uint32_t a3,
    uint32_t b0, uint32_t b1)
{
    asm volatile(
        "mma.sync.aligned.m16n8k16.row.col.f32.bf16.bf16.f32 "
        "{%0,%1,%2,%3}, {%4,%5,%6,%7}, {%8,%9}, {%0,%1,%2,%3};\n"
        : "+f"(c0), "+f"(c1), "+f"(c2), "+f"(c3)
        : "r"(a0), "r"(a1), "r"(a2), "r"(a3), "r"(b0), "r"(b1));
}

#define KC 32
#define ROWP 40                 // 80B smem rows
#define TILE_BYTES (128 * ROWP * 2)   // 10240
#define STAGE_BYTES (4 * TILE_BYTES)  // 40960

__device__ __forceinline__ void cp_tile(uint32_t sbase,
    const __nv_bfloat16* __restrict__ g, int row0, int c0, int tid)
{
#pragma unroll
    for (int l = 0; l < 2; l++) {
        int id = l * 256 + tid;
        int r = id >> 2, s = id & 3;
        const void* src = g + (size_t)(row0 + r) * FEAT + c0 * KC + s * 8;
        uint32_t dst = sbase + r * 80 + s * 16;
        asm volatile("cp.async.cg.shared.global [%0], [%1], 16;"
                     :: "r"(dst), "l"(src));
    }
}

__global__ __launch_bounds__(256) void sge_gemm_mma(int M)
{
    extern __shared__ char gsm[];
    uint32_t sb = smem_u32(gsm);
    const int tid = threadIdx.x;
    const int wid = tid >> 5, lane = tid & 31;
    const int g = lane >> 2, t = lane & 3;
    const int wm = wid & 1, wn = wid >> 1;
    const int M0 = blockIdx.y * 128, N0 = blockIdx.x * 128;
    const int warpM = wm * 64, warpN = wn * 32;

    float acc[4][4][4];
#pragma unroll
    for (int mi = 0; mi < 4; mi++)
#pragma unroll
        for (int ni = 0; ni < 4; ni++)
#pragma unroll
            for (int r = 0; r < 4; r++) acc[mi][ni][r] = 0.f;

    // prefetch chunk 0 into buffer 0
    cp_tile(sb + 0 * TILE_BYTES, g_xhi,  M0, 0, tid);
    cp_tile(sb + 1 * TILE_BYTES, g_xlo,  M0, 0, tid);
    cp_tile(sb + 2 * TILE_BYTES, g_wthi, N0, 0, tid);
    cp_tile(sb + 3 * TILE_BYTES, g_wtlo, N0, 0, tid);
    asm volatile("cp.async.commit_group;");

    for (int c = 0; c < FEAT / KC; c++) {
        if (c < FEAT / KC - 1) {
            uint32_t nb = sb + ((c + 1) & 1) * STAGE_BYTES;
            cp_tile(nb + 0 * TILE_BYTES, g_xhi,  M0, c + 1, tid);
            cp_tile(nb + 1 * TILE_BYTES, g_xlo,  M0, c + 1, tid);
            cp_tile(nb + 2 * TILE_BYTES, g_wthi, N0, c + 1, tid);
            cp_tile(nb + 3 * TILE_BYTES, g_wtlo, N0, c + 1, tid);
            asm volatile("cp.async.commit_group;");
            asm volatile("cp.async.wait_group 1;");
        } else {
            asm volatile("cp.async.wait_group 0;");
        }
        __syncthreads();

        const char* base = gsm + (c & 1) * STAGE_BYTES;
        const __nv_bfloat16* Ah = (const __nv_bfloat16*)(base + 0 * TILE_BYTES);
        const __nv_bfloat16* Al = (const __nv_bfloat16*)(base + 1 * TILE_BYTES);
        const __nv_bfloat16* Bh = (const __nv_bfloat16*)(base + 2 * TILE_BYTES);
        const __nv_bfloat16* Bl = (const __nv_bfloat16*)(base + 3 * TILE_BYTES);

#pragma unroll
        for (int ks = 0; ks < 2; ks++) {
            const int kb = ks * 16;
            uint32_t bh[4][2], bl[4][2];
#pragma unroll
            for (int ni = 0; ni < 4; ni++) {
                int nr = warpN + ni * 8 + g;
                bh[ni][0] = *(const uint32_t*)&Bh[nr * ROWP + kb + 2 * t];
                bh[ni][1] = *(const uint32_t*)&Bh[nr * ROWP + kb + 2 * t + 8];
                bl[ni][0] = *(const uint32_t*)&Bl[nr * ROWP + kb + 2 * t];
                bl[ni][1] = *(const uint32_t*)&Bl[nr * ROWP + kb + 2 * t + 8];
            }
            uint32_t af[4][4];
#pragma unroll
            for (int mi = 0; mi < 4; mi++) {
                int mr = warpM + mi * 16;
                af[mi][0] = *(const uint32_t*)&Ah[(mr + g) * ROWP + kb + 2 * t];
                af[mi][1] = *(const uint32_t*)&Ah[(mr + g + 8) * ROWP + kb + 2 * t];
                af[mi][2] = *(const uint32_t*)&Ah[(mr + g) * ROWP + kb + 2 * t + 8];
                af[mi][3] = *(const uint32_t*)&Ah[(mr + g + 8) * ROWP + kb + 2 * t + 8];
            }
#pragma unroll
            for (int mi = 0; mi < 4; mi++)
#pragma unroll
                for (int ni = 0; ni < 4; ni++) {
                    mma16816(acc[mi][ni][0], acc[mi][ni][1], acc[mi][ni][2], acc[mi][ni][3],
                             af[mi][0], af[mi][1], af[mi][2], af[mi][3],
                             bh[ni][0], bh[ni][1]);
                    mma16816(acc[mi][ni][0], acc[mi][ni][1], acc[mi][ni][2], acc[mi][ni][3],
                             af[mi][0], af[mi][1], af[mi][2], af[mi][3],
                             bl[ni][0], bl[ni][1]);
                }
#pragma unroll
            for (int mi = 0; mi < 4; mi++) {
                int mr = warpM + mi * 16;
                af[mi][0] = *(const uint32_t*)&Al[(mr + g) * ROWP + kb + 2 * t];
                af[mi][1] = *(const uint32_t*)&Al[(mr + g + 8) * ROWP + kb + 2 * t];
                af[mi][2] = *(const uint32_t*)&Al[(mr + g) * ROWP + kb + 2 * t + 8];
                af[mi][3] = *(const uint32_t*)&Al[(mr + g + 8) * ROWP + kb + 2 * t + 8];
            }
#pragma unroll
            for (int mi = 0; mi < 4; mi++)
#pragma unroll
                for (int ni = 0; ni < 4; ni++)
                    mma16816(acc[mi][ni][0], acc[mi][ni][1], acc[mi][ni][2], acc[mi][ni][3],
                             af[mi][0], af[mi][1], af[mi][2], af[mi][3],
                             bh[ni][0], bh[ni][1]);
        }
        __syncthreads();
    }

#pragma unroll
    for (int mi = 0; mi < 4; mi++) {
        int r0 = M0 + warpM + mi * 16 + g;
#pragma unroll
        for (int ni = 0; ni < 4; ni++) {
            int col = N0 + warpN + ni * 8 + 2 * t;
            if (r0 < M)
                *(float2*)&g_z[(size_t)r0 * EMB + col] =
                    make_float2(acc[mi][ni][0], acc[mi][ni][1]);
            if (r0 + 8 < M)
                *(float2*)&g_z[(size_t)(r0 + 8) * EMB + col] =
                    make_float2(acc[mi][ni][2], acc[mi][ni][3]);
        }
    }
}

// ---------------- pass 1: log2-domain Sinkhorn, fused per-iter cost ----------
__global__ __launch_bounds__(128) void sge_sinkhorn_pass1(
    const int* __restrict__ ep, const int* __restrict__ en, int E)
{
    // CshT[warp][j][i] = SCALE * C_ij  (transposed, pad 36 -> conflict-free
    // float4 row loads). bsh overlays the front of CshT during setup.
    __shared__ __align__(16) float CshT[PPB][NPTS][36];
    __shared__ __align__(16) float vsh[PPB][NPTS];
    __shared__ __align__(16) float ush[PPB][NPTS];
    const int warp = threadIdx.x >> 5, lane = threadIdx.x & 31;
    const int p = blockIdx.x * PPB + warp;
    if (p >= 2 * E) return;
    const int batch = (p >= E) ? 1 : 0;
    const int e = p - batch * E;
    const int* edges = batch ? en : ep;
    const int nx = edges[e];
    const int ny = edges[E + e];

    float (*bsh)[SDIM] = (float(*)[SDIM]) & CshT[warp][0][0];

    float a[SDIM];
    {
        const float4* ap = (const float4*)(g_z + (size_t)nx * EMB + lane * SDIM);
        const float4* bp = (const float4*)(g_z + (size_t)ny * EMB + lane * SDIM);
#pragma unroll
        for (int q = 0; q < 4; q++) {
            float4 av = ap[q];
            a[q * 4 + 0] = av.x; a[q * 4 + 1] = av.y;
            a[q * 4 + 2] = av.z; a[q * 4 + 3] = av.w;
            *(float4*)&bsh[lane][q * 4] = bp[q];
        }
    }
    __syncwarp();

    // scaled cost row: C2row[j] = SCALE * ||a_lane - b_j||^2
    float C2row[NPTS];
#pragma unroll 8
    for (int j = 0; j < NPTS; j++) {
        float c = 0.f;
#pragma unroll
        for (int d = 0; d < SDIM; d++) {
            float df = a[d] - bsh[j][d];
            c = fmaf(df, df, c);
        }
        C2row[j] = c * SCALE;
    }
    __syncwarp();   // all bsh reads done before overwriting with CshT
#pragma unroll
    for (int j = 0; j < NPTS; j++) CshT[warp][j][lane] = C2row[j];

    float U = 0.f, V = 0.f;

    for (int t = 0; t < MAX_ITER; t++) {
        vsh[warp][lane] = V;
        __syncwarp();
        // ---- u-half: U_i = K2 - (m + log2 sum_j 2^(V_j - C2_ij - m)) ----
        float m = -1e30f;
#pragma unroll
        for (int j4 = 0; j4 < 8; j4++) {
            float4 v4 = *(const float4*)&vsh[warp][j4 * 4];
            float t0 = v4.x - C2row[j4 * 4 + 0];
            float t1 = v4.y - C2row[j4 * 4 + 1];
            float t2 = v4.z - C2row[j4 * 4 + 2];
            float t3 = v4.w - C2row[j4 * 4 + 3];
            m = fmaxf(m, fmaxf(fmaxf(t0, t1), fmaxf(t2, t3)));
        }
        float s = 0.f;
#pragma unroll
        for (int j4 = 0; j4 < 8; j4++) {
            float4 v4 = *(const float4*)&vsh[warp][j4 * 4];
            float e0 = ex2(v4.x - C2row[j4 * 4 + 0] - m);
            float e1 = ex2(v4.y - C2row[j4 * 4 + 1] - m);
            float e2 = ex2(v4.z - C2row[j4 * 4 + 2] - m);
            float e3 = ex2(v4.w - C2row[j4 * 4 + 3] - m);
            s += (e0 + e1) + (e2 + e3);
        }
        float Unew = K2LOG - (m + lg2(s));
        float dU = fabsf(Unew - U);
        U = Unew;
#pragma unroll
        for (int off = 16; off; off >>= 1)
            dU += __shfl_xor_sync(0xffffffffu, dU, off);
        ush[warp][lane] = U;
        __syncwarp();
        // ---- v-half (lane = column j) with fused cost ----
        float m2 = -1e30f;
#pragma unroll
        for (int i4 = 0; i4 < 8; i4++) {
            float4 u4 = *(const float4*)&ush[warp][i4 * 4];
            float4 c4 = *(const float4*)&CshT[warp][lane][i4 * 4];
            float t0 = u4.x - c4.x, t1 = u4.y - c4.y;
            float t2 = u4.z - c4.z, t3 = u4.w - c4.w;
            m2 = fmaxf(m2, fmaxf(fmaxf(t0, t1), fmaxf(t2, t3)));
        }
        float s2 = 0.f, sc = 0.f;
#pragma unroll
        for (int i4 = 0; i4 < 8; i4++) {
            float4 u4 = *(const float4*)&ush[warp][i4 * 4];
            float4 c4 = *(const float4*)&CshT[warp][lane][i4 * 4];
            float e0 = ex2(u4.x - c4.x - m2);
            float e1 = ex2(u4.y - c4.y - m2);
            float e2 = ex2(u4.z - c4.z - m2);
            float e3 = ex2(u4.w - c4.w - m2);
            s2 += (e0 + e1) + (e2 + e3);
            sc = fmaf(e0, c4.x, fmaf(e1, c4.y, fmaf(e2, c4.z, fmaf(e3, c4.w, sc))));
        }
        V = K2LOG - (m2 + lg2(s2));
        // column j's share of sum(pi*C); sc is in scaled-C units -> /SCALE
        float costl = NU_TILDE * __fdividef(sc, s2 * SCALE);
#pragma unroll
        for (int off = 16; off; off >>= 1)
            costl += __shfl_xor_sync(0xffffffffu, costl, off);
        if (lane == 0) {
            g_cost[p * MAX_ITER + t] = costl;
            atomicAdd(&g_err[batch * MAX_ITER + t], dU);
        }
        __syncwarp();
    }
}

// ---------------- reduce: pick iteration T-1 cost, accumulate loss -----------
__global__ __launch_bounds__(256) void sge_reduce(int E)
{
    __shared__ double sd[256];
    __shared__ int Tsh[2];
    if (threadIdx.x < 2) {
        int b = threadIdx.x;
        int T = MAX_ITER;
        float invE = 1.0f / (float)E;
        for (int t = 0; t < MAX_ITER; t++)
            if (g_err[b * MAX_ITER + t] * invE < THRESH_SCALED) { T = t + 1; break; }
        Tsh[b] = T;
    }
    __syncthreads();
    int p = blockIdx.x * 256 + threadIdx.x;
    double con = 0.0;
    if (p < 2 * E) {
        int b = (p >= E) ? 1 : 0;
        float c = g_cost[p * MAX_ITER + Tsh[b] - 1];
        float energy = -c;
        con = b ? (double)__expf(energy) : (double)energy * (double)energy;
    }
    sd[threadIdx.x] = con;
    __syncthreads();
    for (int s2 = 128; s2; s2 >>= 1) {
        if (threadIdx.x < s2) sd[threadIdx.x] += sd[threadIdx.x + s2];
        __syncthreads();
    }
    if (threadIdx.x == 0) atomicAdd(&g_accd, sd[0]);
}

// ---------------- finalize ---------------------------------------------------
__global__ void sge_finalize_kernel(float* out, int out_size, int E)
{
    float loss = (float)(g_accd / (double)E);
    for (int i = threadIdx.x; i < out_size; i += blockDim.x) out[i] = loss;
}

// ---------------- launch -----------------------------------------------------
extern "C" void kernel_launch(void* const* d_in, const int* in_sizes, int n_in,
                              void* d_out, int out_size)
{
    const float* x = (const float*)d_in[0];
    const float* W = (const float*)d_in[1];
    const int* ep  = (const int*)d_in[2];
    const int* en  = (const int*)d_in[3];
    int M = in_sizes[0] / FEAT;
    if (M > MAX_NODES) M = MAX_NODES;
    int E = in_sizes[2] / 2;
    if (E > MAX_E) E = MAX_E;

    static bool attr_set = false;
    if (!attr_set) {
        cudaFuncSetAttribute(sge_gemm_mma,
                             cudaFuncAttributeMaxDynamicSharedMemorySize,
                             2 * STAGE_BYTES);
        attr_set = true;
    }

    sge_convert_x<<<(MPAD * FEAT + 255) / 256, 256>>>(x, M);
    sge_convert_w<<<(EMB * FEAT + 255) / 256, 256>>>(W);
    sge_gemm_mma<<<dim3(EMB / 128, MPAD / 128), 256, 2 * STAGE_BYTES>>>(M);
    int nblocks = (2 * E + PPB - 1) / PPB;
    sge_sinkhorn_pass1<<<nblocks, 128>>>(ep, en, E);
    sge_reduce<<<(2 * E + 255) / 256, 256>>>(E);
    sge_finalize_kernel<<<1, 32>>>((float*)d_out, out_size, E);
}

// round 9
// speedup vs baseline: 1.9708x; 1.5447x over previous
#include <cuda_runtime.h>
#include <cuda_bf16.h>
#include <cstdint>
#include <math.h>

#define FEAT 256
#define EMB 512
#define NPTS 32
#define SDIM 16
#define MAX_E 4096
#define MAX_NODES 10000
#define MPAD 10112          // 79 * 128
#define EPS 0.1f
#define MAX_ITER 10
#define PPB 4               // pairs (warps) per block in sinkhorn pass1
#define NU_TILDE 0.03125001f          // 1/32 + 1e-8
#define SCALE 14.426950408889634f     // (1/EPS)*log2(e)
#define K2LOG (-4.9999995385f)        // log2(NU_TILDE)
#define THRESH_SCALED 1.4426950408889634f  // 0.1 * SCALE

// ---------------- scratch (static device globals; no allocs) ----------------
__device__ __align__(256) float         g_z[(size_t)MPAD * EMB];
__device__ __align__(256) __nv_bfloat16 g_xhi[(size_t)MPAD * FEAT];
__device__ __align__(256) __nv_bfloat16 g_xlo[(size_t)MPAD * FEAT];
__device__ __align__(256) __nv_bfloat16 g_wthi[(size_t)EMB * FEAT];   // W^T [n][k]
__device__ __align__(256) __nv_bfloat16 g_wtlo[(size_t)EMB * FEAT];
__device__ __align__(256) float         g_cost[2 * MAX_E * MAX_ITER];
__device__ float  g_err[2 * MAX_ITER];
__device__ double g_accd;

// ---------------- fast math wrappers ----------------------------------------
__device__ __forceinline__ float ex2(float x) {
    float y; asm("ex2.approx.ftz.f32 %0, %1;" : "=f"(y) : "f"(x)); return y;
}
__device__ __forceinline__ float lg2(float x) {
    float y; asm("lg2.approx.ftz.f32 %0, %1;" : "=f"(y) : "f"(x)); return y;
}
__device__ __forceinline__ uint32_t smem_u32(const void* p) {
    uint32_t a;
    asm("{ .reg .u64 t; cvta.to.shared.u64 t, %1; cvt.u32.u64 %0, t; }"
        : "=r"(a) : "l"(p));
    return a;
}

// ---------------- convert kernels -------------------------------------------
__global__ __launch_bounds__(256) void sge_convert_x(const float* __restrict__ x, int M)
{
    int idx = blockIdx.x * 256 + threadIdx.x;
    if (idx < 2 * MAX_ITER) g_err[idx] = 0.f;
    if (idx == 2 * MAX_ITER) g_accd = 0.0;
    if (idx >= MPAD * FEAT) return;
    int row = idx / FEAT;
    float v = (row < M) ? x[idx] : 0.f;
    __nv_bfloat16 hi = __float2bfloat16(v);
    __nv_bfloat16 lo = __float2bfloat16(v - __bfloat162float(hi));
    g_xhi[idx] = hi;
    g_xlo[idx] = lo;
}

__global__ __launch_bounds__(256) void sge_convert_w(const float* __restrict__ W)
{
    int idx = blockIdx.x * 256 + threadIdx.x;
    if (idx >= EMB * FEAT) return;
    int n = idx / FEAT, k = idx % FEAT;
    float v = W[(size_t)k * EMB + n];
    __nv_bfloat16 hi = __float2bfloat16(v);
    __nv_bfloat16 lo = __float2bfloat16(v - __bfloat162float(hi));
    g_wthi[idx] = hi;
    g_wtlo[idx] = lo;
}

// ---------------- HMMA GEMM: z = x @ W via bf16 hi/lo split -----------------
__device__ __forceinline__ void mma16816(
    float& c0, float& c1, float& c2, float& c3,
    uint32_t a0, uint32_t a1, uint32_t a2, uint32_t a3,
    uint32_t b0, uint32_t b1)
{
    asm volatile(
        "mma.sync.aligned.m16n8k16.row.col.f32.bf16.bf16.f32 "
        "{%0,%1,%2,%3}, {%4,%5,%6,%7}, {%8,%9}, {%0,%1,%2,%3};\n"
        : "+f"(c0), "+f"(c1), "+f"(c2), "+f"(c3)
        : "r"(a0), "r"(a1), "r"(a2), "r"(a3), "r"(b0), "r"(b1));
}

#define KC 32
#define ROWP 40                 // 80B smem rows
#define TILE_BYTES (128 * ROWP * 2)   // 10240
#define STAGE_BYTES (4 * TILE_BYTES)  // 40960

__device__ __forceinline__ void cp_tile(uint32_t sbase,
    const __nv_bfloat16* __restrict__ g, int row0, int c0, int tid)
{
#pragma unroll
    for (int l = 0; l < 2; l++) {
        int id = l * 256 + tid;
        int r = id >> 2, s = id & 3;
        const void* src = g + (size_t)(row0 + r) * FEAT + c0 * KC + s * 8;
        uint32_t dst = sbase + r * 80 + s * 16;
        asm volatile("cp.async.cg.shared.global [%0], [%1], 16;"
                     :: "r"(dst), "l"(src));
    }
}

__global__ __launch_bounds__(256) void sge_gemm_mma(int M)
{
    extern __shared__ char gsm[];
    uint32_t sb = smem_u32(gsm);
    const int tid = threadIdx.x;
    const int wid = tid >> 5, lane = tid & 31;
    const int g = lane >> 2, t = lane & 3;
    const int wm = wid & 1, wn = wid >> 1;
    const int M0 = blockIdx.y * 128, N0 = blockIdx.x * 128;
    const int warpM = wm * 64, warpN = wn * 32;

    float acc[4][4][4];
#pragma unroll
    for (int mi = 0; mi < 4; mi++)
#pragma unroll
        for (int ni = 0; ni < 4; ni++)
#pragma unroll
            for (int r = 0; r < 4; r++) acc[mi][ni][r] = 0.f;

    cp_tile(sb + 0 * TILE_BYTES, g_xhi,  M0, 0, tid);
    cp_tile(sb + 1 * TILE_BYTES, g_xlo,  M0, 0, tid);
    cp_tile(sb + 2 * TILE_BYTES, g_wthi, N0, 0, tid);
    cp_tile(sb + 3 * TILE_BYTES, g_wtlo, N0, 0, tid);
    asm volatile("cp.async.commit_group;");

    for (int c = 0; c < FEAT / KC; c++) {
        if (c < FEAT / KC - 1) {
            uint32_t nb = sb + ((c + 1) & 1) * STAGE_BYTES;
            cp_tile(nb + 0 * TILE_BYTES, g_xhi,  M0, c + 1, tid);
            cp_tile(nb + 1 * TILE_BYTES, g_xlo,  M0, c + 1, tid);
            cp_tile(nb + 2 * TILE_BYTES, g_wthi, N0, c + 1, tid);
            cp_tile(nb + 3 * TILE_BYTES, g_wtlo, N0, c + 1, tid);
            asm volatile("cp.async.commit_group;");
            asm volatile("cp.async.wait_group 1;");
        } else {
            asm volatile("cp.async.wait_group 0;");
        }
        __syncthreads();

        const char* base = gsm + (c & 1) * STAGE_BYTES;
        const __nv_bfloat16* Ah = (const __nv_bfloat16*)(base + 0 * TILE_BYTES);
        const __nv_bfloat16* Al = (const __nv_bfloat16*)(base + 1 * TILE_BYTES);
        const __nv_bfloat16* Bh = (const __nv_bfloat16*)(base + 2 * TILE_BYTES);
        const __nv_bfloat16* Bl = (const __nv_bfloat16*)(base + 3 * TILE_BYTES);

#pragma unroll
        for (int ks = 0; ks < 2; ks++) {
            const int kb = ks * 16;
            uint32_t bh[4][2], bl[4][2];
#pragma unroll
            for (int ni = 0; ni < 4; ni++) {
                int nr = warpN + ni * 8 + g;
                bh[ni][0] = *(const uint32_t*)&Bh[nr * ROWP + kb + 2 * t];
                bh[ni][1] = *(const uint32_t*)&Bh[nr * ROWP + kb + 2 * t + 8];
                bl[ni][0] = *(const uint32_t*)&Bl[nr * ROWP + kb + 2 * t];
                bl[ni][1] = *(const uint32_t*)&Bl[nr * ROWP + kb + 2 * t + 8];
            }
            uint32_t af[4][4];
#pragma unroll
            for (int mi = 0; mi < 4; mi++) {
                int mr = warpM + mi * 16;
                af[mi][0] = *(const uint32_t*)&Ah[(mr + g) * ROWP + kb + 2 * t];
                af[mi][1] = *(const uint32_t*)&Ah[(mr + g + 8) * ROWP + kb + 2 * t];
                af[mi][2] = *(const uint32_t*)&Ah[(mr + g) * ROWP + kb + 2 * t + 8];
                af[mi][3] = *(const uint32_t*)&Ah[(mr + g + 8) * ROWP + kb + 2 * t + 8];
            }
#pragma unroll
            for (int mi = 0; mi < 4; mi++)
#pragma unroll
                for (int ni = 0; ni < 4; ni++) {
                    mma16816(acc[mi][ni][0], acc[mi][ni][1], acc[mi][ni][2], acc[mi][ni][3],
                             af[mi][0], af[mi][1], af[mi][2], af[mi][3],
                             bh[ni][0], bh[ni][1]);
                    mma16816(acc[mi][ni][0], acc[mi][ni][1], acc[mi][ni][2], acc[mi][ni][3],
                             af[mi][0], af[mi][1], af[mi][2], af[mi][3],
                             bl[ni][0], bl[ni][1]);
                }
#pragma unroll
            for (int mi = 0; mi < 4; mi++) {
                int mr = warpM + mi * 16;
                af[mi][0] = *(const uint32_t*)&Al[(mr + g) * ROWP + kb + 2 * t];
                af[mi][1] = *(const uint32_t*)&Al[(mr + g + 8) * ROWP + kb + 2 * t];
                af[mi][2] = *(const uint32_t*)&Al[(mr + g) * ROWP + kb + 2 * t + 8];
                af[mi][3] = *(const uint32_t*)&Al[(mr + g + 8) * ROWP + kb + 2 * t + 8];
            }
#pragma unroll
            for (int mi = 0; mi < 4; mi++)
#pragma unroll
                for (int ni = 0; ni < 4; ni++)
                    mma16816(acc[mi][ni][0], acc[mi][ni][1], acc[mi][ni][2], acc[mi][ni][3],
                             af[mi][0], af[mi][1], af[mi][2], af[mi][3],
                             bh[ni][0], bh[ni][1]);
        }
        __syncthreads();
    }

#pragma unroll
    for (int mi = 0; mi < 4; mi++) {
        int r0 = M0 + warpM + mi * 16 + g;
#pragma unroll
        for (int ni = 0; ni < 4; ni++) {
            int col = N0 + warpN + ni * 8 + 2 * t;
            if (r0 < M)
                *(float2*)&g_z[(size_t)r0 * EMB + col] =
                    make_float2(acc[mi][ni][0], acc[mi][ni][1]);
            if (r0 + 8 < M)
                *(float2*)&g_z[(size_t)(r0 + 8) * EMB + col] =
                    make_float2(acc[mi][ni][2], acc[mi][ni][3]);
        }
    }
}

// ---------------- pass 1: log2-domain Sinkhorn, deferred reductions ----------
__global__ __launch_bounds__(128) void sge_sinkhorn_pass1(
    const int* __restrict__ ep, const int* __restrict__ en, int E)
{
    __shared__ __align__(16) float CshT[PPB][NPTS][36];
    __shared__ __align__(16) float vsh[PPB][NPTS];
    __shared__ __align__(16) float ush[PPB][NPTS];
    // per-lane deferred reduction buffers: [0]=dU, [1]=cost; pad 33 rows
    __shared__ __align__(16) float redsh[PPB][2][MAX_ITER][33];
    const int warp = threadIdx.x >> 5, lane = threadIdx.x & 31;
    const int p = blockIdx.x * PPB + warp;
    if (p >= 2 * E) return;
    const int batch = (p >= E) ? 1 : 0;
    const int e = p - batch * E;
    const int* edges = batch ? en : ep;
    const int nx = edges[e];
    const int ny = edges[E + e];

    float (*bsh)[SDIM] = (float(*)[SDIM]) & CshT[warp][0][0];

    float a[SDIM];
    {
        const float4* ap = (const float4*)(g_z + (size_t)nx * EMB + lane * SDIM);
        const float4* bp = (const float4*)(g_z + (size_t)ny * EMB + lane * SDIM);
#pragma unroll
        for (int q = 0; q < 4; q++) {
            float4 av = ap[q];
            a[q * 4 + 0] = av.x; a[q * 4 + 1] = av.y;
            a[q * 4 + 2] = av.z; a[q * 4 + 3] = av.w;
            *(float4*)&bsh[lane][q * 4] = bp[q];
        }
    }
    __syncwarp();

    // scaled cost row: C2row[j] = SCALE * ||a_lane - b_j||^2
    float C2row[NPTS];
#pragma unroll 8
    for (int j = 0; j < NPTS; j++) {
        float c = 0.f;
#pragma unroll
        for (int d = 0; d < SDIM; d++) {
            float df = a[d] - bsh[j][d];
            c = fmaf(df, df, c);
        }
        C2row[j] = c * SCALE;
    }
    __syncwarp();   // all bsh reads done before overwriting with CshT
#pragma unroll
    for (int j = 0; j < NPTS; j++) CshT[warp][j][lane] = C2row[j];

    float U = 0.f, V = 0.f;

    for (int t = 0; t < MAX_ITER; t++) {
        vsh[warp][lane] = V;
        __syncwarp();
        // ---- u-half: U_i = K2 - (m + log2 sum_j 2^(V_j - C2_ij - m)) ----
        float ma = -1e30f, mb = -1e30f;
#pragma unroll
        for (int j4 = 0; j4 < 8; j4 += 2) {
            float4 va = *(const float4*)&vsh[warp][j4 * 4];
            float4 vb = *(const float4*)&vsh[warp][j4 * 4 + 4];
            ma = fmaxf(ma, fmaxf(fmaxf(va.x - C2row[j4 * 4 + 0], va.y - C2row[j4 * 4 + 1]),
                                 fmaxf(va.z - C2row[j4 * 4 + 2], va.w - C2row[j4 * 4 + 3])));
            mb = fmaxf(mb, fmaxf(fmaxf(vb.x - C2row[j4 * 4 + 4], vb.y - C2row[j4 * 4 + 5]),
                                 fmaxf(vb.z - C2row[j4 * 4 + 6], vb.w - C2row[j4 * 4 + 7])));
        }
        float m = fmaxf(ma, mb);
        float sa = 0.f, sb = 0.f;
#pragma unroll
        for (int j4 = 0; j4 < 8; j4 += 2) {
            float4 va = *(const float4*)&vsh[warp][j4 * 4];
            float4 vb = *(const float4*)&vsh[warp][j4 * 4 + 4];
            float e0 = ex2(va.x - C2row[j4 * 4 + 0] - m);
            float e1 = ex2(va.y - C2row[j4 * 4 + 1] - m);
            float e2 = ex2(va.z - C2row[j4 * 4 + 2] - m);
            float e3 = ex2(va.w - C2row[j4 * 4 + 3] - m);
            float f0 = ex2(vb.x - C2row[j4 * 4 + 4] - m);
            float f1 = ex2(vb.y - C2row[j4 * 4 + 5] - m);
            float f2 = ex2(vb.z - C2row[j4 * 4 + 6] - m);
            float f3 = ex2(vb.w - C2row[j4 * 4 + 7] - m);
            sa += (e0 + e1) + (e2 + e3);
            sb += (f0 + f1) + (f2 + f3);
        }
        float Unew = K2LOG - (m + lg2(sa + sb));
        float dU = fabsf(Unew - U);
        U = Unew;
        redsh[warp][0][t][lane] = dU;      // deferred err reduction
        ush[warp][lane] = U;
        __syncwarp();
        // ---- v-half (lane = column j) with fused cost ----
        float m2a = -1e30f, m2b = -1e30f;
#pragma unroll
        for (int i4 = 0; i4 < 8; i4 += 2) {
            float4 ua = *(const float4*)&ush[warp][i4 * 4];
            float4 ub = *(const float4*)&ush[warp][i4 * 4 + 4];
            float4 ca = *(const float4*)&CshT[warp][lane][i4 * 4];
            float4 cb = *(const float4*)&CshT[warp][lane][i4 * 4 + 4];
            m2a = fmaxf(m2a, fmaxf(fmaxf(ua.x - ca.x, ua.y - ca.y),
                                   fmaxf(ua.z - ca.z, ua.w - ca.w)));
            m2b = fmaxf(m2b, fmaxf(fmaxf(ub.x - cb.x, ub.y - cb.y),
                                   fmaxf(ub.z - cb.z, ub.w - cb.w)));
        }
        float m2 = fmaxf(m2a, m2b);
        float s2a = 0.f, s2b = 0.f, sca = 0.f, scb = 0.f;
#pragma unroll
        for (int i4 = 0; i4 < 8; i4 += 2) {
            float4 ua = *(const float4*)&ush[warp][i4 * 4];
            float4 ub = *(const float4*)&ush[warp][i4 * 4 + 4];
            float4 ca = *(const float4*)&CshT[warp][lane][i4 * 4];
            float4 cb = *(const float4*)&CshT[warp][lane][i4 * 4 + 4];
            float e0 = ex2(ua.x - ca.x - m2);
            float e1 = ex2(ua.y - ca.y - m2);
            float e2 = ex2(ua.z - ca.z - m2);
            float e3 = ex2(ua.w - ca.w - m2);
            float f0 = ex2(ub.x - cb.x - m2);
            float f1 = ex2(ub.y - cb.y - m2);
            float f2 = ex2(ub.z - cb.z - m2);
            float f3 = ex2(ub.w - cb.w - m2);
            s2a += (e0 + e1) + (e2 + e3);
            s2b += (f0 + f1) + (f2 + f3);
            sca += fmaf(e0, ca.x, e1 * ca.y) + fmaf(e2, ca.z, e3 * ca.w);
            scb += fmaf(f0, cb.x, f1 * cb.y) + fmaf(f2, cb.z, f3 * cb.w);
        }
        float s2 = s2a + s2b;
        V = K2LOG - (m2 + lg2(s2));
        // column j's share of sum(pi*C); sc in scaled-C units -> /SCALE
        redsh[warp][1][t][lane] = NU_TILDE * __fdividef(sca + scb, s2 * SCALE);
        // no trailing syncwarp needed: next iteration's vsh store is ordered
        // by the syncwarp after it; ush/vsh are distinct arrays.
    }
    __syncwarp();

    // deferred reductions: lanes 0..9 -> err[t], lanes 10..19 -> cost[t]
    if (lane < 2 * MAX_ITER) {
        const int which = (lane < MAX_ITER) ? 0 : 1;
        const int t = (lane < MAX_ITER) ? lane : lane - MAX_ITER;
        float ssum = 0.f;
#pragma unroll
        for (int i = 0; i < NPTS; i++) ssum += redsh[warp][which][t][i];
        if (which == 0) atomicAdd(&g_err[batch * MAX_ITER + t], ssum);
        else            g_cost[p * MAX_ITER + t] = ssum;
    }
}

// ---------------- reduce: pick iteration T-1 cost, accumulate loss -----------
__global__ __launch_bounds__(256) void sge_reduce(int E)
{
    __shared__ double sd[256];
    __shared__ int Tsh[2];
    if (threadIdx.x < 2) {
        int b = threadIdx.x;
        int T = MAX_ITER;
        float invE = 1.0f / (float)E;
        for (int t = 0; t < MAX_ITER; t++)
            if (g_err[b * MAX_ITER + t] * invE < THRESH_SCALED) { T = t + 1; break; }
        Tsh[b] = T;
    }
    __syncthreads();
    int p = blockIdx.x * 256 + threadIdx.x;
    double con = 0.0;
    if (p < 2 * E) {
        int b = (p >= E) ? 1 : 0;
        float c = g_cost[p * MAX_ITER + Tsh[b] - 1];
        float energy = -c;
        con = b ? (double)__expf(energy) : (double)energy * (double)energy;
    }
    sd[threadIdx.x] = con;
    __syncthreads();
    for (int s2 = 128; s2; s2 >>= 1) {
        if (threadIdx.x < s2) sd[threadIdx.x] += sd[threadIdx.x + s2];
        __syncthreads();
    }
    if (threadIdx.x == 0) atomicAdd(&g_accd, sd[0]);
}

// ---------------- finalize ---------------------------------------------------
__global__ void sge_finalize_kernel(float* out, int out_size, int E)
{
    float loss = (float)(g_accd / (double)E);
    for (int i = threadIdx.x; i < out_size; i += blockDim.x) out[i] = loss;
}

// ---------------- launch -----------------------------------------------------
extern "C" void kernel_launch(void* const* d_in, const int* in_sizes, int n_in,
                              void* d_out, int out_size)
{
    const float* x = (const float*)d_in[0];
    const float* W = (const float*)d_in[1];
    const int* ep  = (const int*)d_in[2];
    const int* en  = (const int*)d_in[3];
    int M = in_sizes[0] / FEAT;
    if (M > MAX_NODES) M = MAX_NODES;
    int E = in_sizes[2] / 2;
    if (E > MAX_E) E = MAX_E;

    static bool attr_set = false;
    if (!attr_set) {
        cudaFuncSetAttribute(sge_gemm_mma,
                             cudaFuncAttributeMaxDynamicSharedMemorySize,
                             2 * STAGE_BYTES);
        attr_set = true;
    }

    sge_convert_x<<<(MPAD * FEAT + 255) / 256, 256>>>(x, M);
    sge_convert_w<<<(EMB * FEAT + 255) / 256, 256>>>(W);
    sge_gemm_mma<<<dim3(EMB / 128, MPAD / 128), 256, 2 * STAGE_BYTES>>>(M);
    int nblocks = (2 * E + PPB - 1) / PPB;
    sge_sinkhorn_pass1<<<nblocks, 128>>>(ep, en, E);
    sge_reduce<<<(2 * E + 255) / 256, 256>>>(E);
    sge_finalize_kernel<<<1, 32>>>((float*)d_out, out_size, E);
}

// round 10
// speedup vs baseline: 2.0237x; 1.0269x over previous
#include <cuda_runtime.h>
#include <cuda_bf16.h>
#include <cstdint>
#include <math.h>

#define FEAT 256
#define EMB 512
#define NPTS 32
#define SDIM 16
#define MAX_E 4096
#define MAX_NODES 10000
#define MPAD 10112          // 79 * 128
#define EPS 0.1f
#define MAX_ITER 10
#define PPB 4               // pairs (warps) per block in sinkhorn pass1
#define NU_TILDE 0.03125001f          // 1/32 + 1e-8
#define SCALE 14.426950408889634f     // (1/EPS)*log2(e)
#define K2LOG (-4.9999995385f)        // log2(NU_TILDE)
#define THRESH_SCALED 1.4426950408889634f  // 0.1 * SCALE

// ---------------- scratch (static device globals; no allocs) ----------------
__device__ __align__(256) float         g_z[(size_t)MPAD * EMB];
__device__ __align__(256) __nv_bfloat16 g_xhi[(size_t)MPAD * FEAT];
__device__ __align__(256) __nv_bfloat16 g_xlo[(size_t)MPAD * FEAT];
__device__ __align__(256) __nv_bfloat16 g_wthi[(size_t)EMB * FEAT];   // W^T [n][k]
__device__ __align__(256) __nv_bfloat16 g_wtlo[(size_t)EMB * FEAT];
__device__ __align__(256) float         g_cost[2 * MAX_E * MAX_ITER];
__device__ float  g_err[2 * MAX_ITER];
__device__ double g_accd;

// ---------------- fast math wrappers ----------------------------------------
__device__ __forceinline__ float ex2(float x) {
    float y; asm("ex2.approx.ftz.f32 %0, %1;" : "=f"(y) : "f"(x)); return y;
}
__device__ __forceinline__ float lg2(float x) {
    float y; asm("lg2.approx.ftz.f32 %0, %1;" : "=f"(y) : "f"(x)); return y;
}
__device__ __forceinline__ uint32_t smem_u32(const void* p) {
    uint32_t a;
    asm("{ .reg .u64 t; cvta.to.shared.u64 t, %1; cvt.u32.u64 %0, t; }"
        : "=r"(a) : "l"(p));
    return a;
}

// ---------------- convert kernels -------------------------------------------
// x: vectorized float4 -> 4x(hi,lo) bf16, coalesced both sides
__global__ __launch_bounds__(256) void sge_convert_x(const float* __restrict__ x, int M)
{
    int i = blockIdx.x * 256 + threadIdx.x;     // group of 4 elements
    if (i < 2 * MAX_ITER) g_err[i] = 0.f;
    if (i == 2 * MAX_ITER) g_accd = 0.0;
    if (i >= (MPAD * FEAT) / 4) return;
    int row = (i * 4) / FEAT;
    float4 v = make_float4(0.f, 0.f, 0.f, 0.f);
    if (row < M) v = *(const float4*)(x + (size_t)i * 4);
    __nv_bfloat16 h[4], l[4];
    float vv[4] = {v.x, v.y, v.z, v.w};
#pragma unroll
    for (int q = 0; q < 4; q++) {
        h[q] = __float2bfloat16(vv[q]);
        l[q] = __float2bfloat16(vv[q] - __bfloat162float(h[q]));
    }
    *(uint2*)(g_xhi + (size_t)i * 4) = *(uint2*)h;
    *(uint2*)(g_xlo + (size_t)i * 4) = *(uint2*)l;
}

// W [k][n] -> W^T [n][k] hi/lo via 32x32 smem transpose (coalesced both sides)
__global__ __launch_bounds__(256) void sge_convert_w(const float* __restrict__ W)
{
    __shared__ float tile[32][33];
    const int k0 = blockIdx.x * 32, n0 = blockIdx.y * 32;
    const int tx = threadIdx.x & 31, ty4 = threadIdx.x >> 5;  // 8 rows/pass
#pragma unroll
    for (int r = 0; r < 4; r++) {
        int k = ty4 + r * 8;
        tile[k][tx] = W[(size_t)(k0 + k) * EMB + n0 + tx];
    }
    __syncthreads();
#pragma unroll
    for (int r = 0; r < 4; r++) {
        int n = ty4 + r * 8;
        float v = tile[tx][n];
        __nv_bfloat16 hi = __float2bfloat16(v);
        __nv_bfloat16 lo = __float2bfloat16(v - __bfloat162float(hi));
        g_wthi[(size_t)(n0 + n) * FEAT + k0 + tx] = hi;
        g_wtlo[(size_t)(n0 + n) * FEAT + k0 + tx] = lo;
    }
}

// ---------------- HMMA GEMM: z = x @ W via bf16 hi/lo split -----------------
__device__ __forceinline__ void mma16816(
    float& c0, float& c1, float& c2, float& c3,
    uint32_t a0, uint32_t a1, uint32_t a2, uint32_t a3,
    uint32_t b0, uint32_t b1)
{
    asm volatile(
        "mma.sync.aligned.m16n8k16.row.col.f32.bf16.bf16.f32 "
        "{%0,%1,%2,%3}, {%4,%5,%6,%7}, {%8,%9}, {%0,%1,%2,%3};\n"
        : "+f"(c0), "+f"(c1), "+f"(c2), "+f"(c3)
        : "r"(a0), "r"(a1), "r"(a2), "r"(a3), "r"(b0), "r"(b1));
}

#define LDM4(r, a) \
    asm volatile("ldmatrix.sync.aligned.m8n8.x4.shared.b16 {%0,%1,%2,%3}, [%4];" \
        : "=r"((r)[0]), "=r"((r)[1]), "=r"((r)[2]), "=r"((r)[3]) : "r"(a))

#define KC 32
#define ROWP 40                 // 80B smem rows (ldmatrix conflict-free)
#define ROWB 80
#define TILE_BYTES (128 * ROWB)       // 10240
#define STAGE_BYTES (4 * TILE_BYTES)  // 40960

__device__ __forceinline__ void cp_tile(uint32_t sbase,
    const __nv_bfloat16* __restrict__ g, int row0, int c0, int tid)
{
#pragma unroll
    for (int l = 0; l < 2; l++) {
        int id = l * 256 + tid;
        int r = id >> 2, s = id & 3;
        const void* src = g + (size_t)(row0 + r) * FEAT + c0 * KC + s * 8;
        uint32_t dst = sbase + r * ROWB + s * 16;
        asm volatile("cp.async.cg.shared.global [%0], [%1], 16;"
                     :: "r"(dst), "l"(src));
    }
}

__global__ __launch_bounds__(256, 2) void sge_gemm_mma(int M)
{
    extern __shared__ char gsm[];
    uint32_t sb = smem_u32(gsm);
    const int tid = threadIdx.x;
    const int wid = tid >> 5, lane = tid & 31;
    const int g = lane >> 2, t = lane & 3;
    const int wm = wid & 1, wn = wid >> 1;
    const int M0 = blockIdx.y * 128, N0 = blockIdx.x * 128;
    const int warpM = wm * 64, warpN = wn * 32;

    // per-lane ldmatrix address offset: row = lane&15, k-half = lane>>4
    const uint32_t loff = (uint32_t)((lane & 15) * ROWB + (lane >> 4) * 16);

    float acc[4][4][4];
#pragma unroll
    for (int mi = 0; mi < 4; mi++)
#pragma unroll
        for (int ni = 0; ni < 4; ni++)
#pragma unroll
            for (int r = 0; r < 4; r++) acc[mi][ni][r] = 0.f;

    cp_tile(sb + 0 * TILE_BYTES, g_xhi,  M0, 0, tid);
    cp_tile(sb + 1 * TILE_BYTES, g_xlo,  M0, 0, tid);
    cp_tile(sb + 2 * TILE_BYTES, g_wthi, N0, 0, tid);
    cp_tile(sb + 3 * TILE_BYTES, g_wtlo, N0, 0, tid);
    asm volatile("cp.async.commit_group;");

    for (int c = 0; c < FEAT / KC; c++) {
        if (c < FEAT / KC - 1) {
            uint32_t nb = sb + ((c + 1) & 1) * STAGE_BYTES;
            cp_tile(nb + 0 * TILE_BYTES, g_xhi,  M0, c + 1, tid);
            cp_tile(nb + 1 * TILE_BYTES, g_xlo,  M0, c + 1, tid);
            cp_tile(nb + 2 * TILE_BYTES, g_wthi, N0, c + 1, tid);
            cp_tile(nb + 3 * TILE_BYTES, g_wtlo, N0, c + 1, tid);
            asm volatile("cp.async.commit_group;");
            asm volatile("cp.async.wait_group 1;");
        } else {
            asm volatile("cp.async.wait_group 0;");
        }
        __syncthreads();

        const uint32_t stage = sb + (c & 1) * STAGE_BYTES;
        const uint32_t ahA = stage + 0 * TILE_BYTES + warpM * ROWB + loff;
        const uint32_t alA = stage + 1 * TILE_BYTES + warpM * ROWB + loff;
        const uint32_t bhA = stage + 2 * TILE_BYTES + warpN * ROWB + loff;
        const uint32_t blA = stage + 3 * TILE_BYTES + warpN * ROWB + loff;

#pragma unroll
        for (int ks = 0; ks < 2; ks++) {
            const uint32_t ko = ks * 32;   // 16 bf16 = 32 bytes
            // B fragments: x4 covers 16 n-rows -> b0/b1 for two ni's
            uint32_t bh[2][4], bl[2][4];
            LDM4(bh[0], bhA + 0 * 16 * ROWB + ko);
            LDM4(bh[1], bhA + 1 * 16 * ROWB + ko);
            LDM4(bl[0], blA + 0 * 16 * ROWB + ko);
            LDM4(bl[1], blA + 1 * 16 * ROWB + ko);
            // A hi fragments
            uint32_t ah[4][4];
#pragma unroll
            for (int mi = 0; mi < 4; mi++)
                LDM4(ah[mi], ahA + mi * 16 * ROWB + ko);
#pragma unroll
            for (int mi = 0; mi < 4; mi++)
#pragma unroll
                for (int ni = 0; ni < 4; ni++) {
                    const int np = ni >> 1, no = ni & 1;
                    mma16816(acc[mi][ni][0], acc[mi][ni][1], acc[mi][ni][2], acc[mi][ni][3],
                             ah[mi][0], ah[mi][1], ah[mi][2], ah[mi][3],
                             bh[np][no], bh[np][no + 2]);
                    mma16816(acc[mi][ni][0], acc[mi][ni][1], acc[mi][ni][2], acc[mi][ni][3],
                             ah[mi][0], ah[mi][1], ah[mi][2], ah[mi][3],
                             bl[np][no], bl[np][no + 2]);
                }
            // A lo fragments
            uint32_t al[4][4];
#pragma unroll
            for (int mi = 0; mi < 4; mi++)
                LDM4(al[mi], alA + mi * 16 * ROWB + ko);
#pragma unroll
            for (int mi = 0; mi < 4; mi++)
#pragma unroll
                for (int ni = 0; ni < 4; ni++) {
                    const int np = ni >> 1, no = ni & 1;
                    mma16816(acc[mi][ni][0], acc[mi][ni][1], acc[mi][ni][2], acc[mi][ni][3],
                             al[mi][0], al[mi][1], al[mi][2], al[mi][3],
                             bh[np][no], bh[np][no + 2]);
                }
        }
        __syncthreads();
    }

#pragma unroll
    for (int mi = 0; mi < 4; mi++) {
        int r0 = M0 + warpM + mi * 16 + g;
#pragma unroll
        for (int ni = 0; ni < 4; ni++) {
            int col = N0 + warpN + ni * 8 + 2 * t;
            if (r0 < M)
                *(float2*)&g_z[(size_t)r0 * EMB + col] =
                    make_float2(acc[mi][ni][0], acc[mi][ni][1]);
            if (r0 + 8 < M)
                *(float2*)&g_z[(size_t)(r0 + 8) * EMB + col] =
                    make_float2(acc[mi][ni][2], acc[mi][ni][3]);
        }
    }
}

// ---------------- pass 1: log2-domain Sinkhorn, deferred reductions ----------
__global__ __launch_bounds__(128) void sge_sinkhorn_pass1(
    const int* __restrict__ ep, const int* __restrict__ en, int E)
{
    __shared__ __align__(16) float CshT[PPB][NPTS][36];
    __shared__ __align__(16) float vsh[PPB][NPTS];
    __shared__ __align__(16) float ush[PPB][NPTS];
    __shared__ __align__(16) float redsh[PPB][2][MAX_ITER][33];
    const int warp = threadIdx.x >> 5, lane = threadIdx.x & 31;
    const int p = blockIdx.x * PPB + warp;
    if (p >= 2 * E) return;
    const int batch = (p >= E) ? 1 : 0;
    const int e = p - batch * E;
    const int* edges = batch ? en : ep;
    const int nx = edges[e];
    const int ny = edges[E + e];

    float (*bsh)[SDIM] = (float(*)[SDIM]) & CshT[warp][0][0];

    float a[SDIM];
    {
        const float4* ap = (const float4*)(g_z + (size_t)nx * EMB + lane * SDIM);
        const float4* bp = (const float4*)(g_z + (size_t)ny * EMB + lane * SDIM);
#pragma unroll
        for (int q = 0; q < 4; q++) {
            float4 av = ap[q];
            a[q * 4 + 0] = av.x; a[q * 4 + 1] = av.y;
            a[q * 4 + 2] = av.z; a[q * 4 + 3] = av.w;
            *(float4*)&bsh[lane][q * 4] = bp[q];
        }
    }
    __syncwarp();

    float C2row[NPTS];
#pragma unroll 8
    for (int j = 0; j < NPTS; j++) {
        float c = 0.f;
#pragma unroll
        for (int d = 0; d < SDIM; d++) {
            float df = a[d] - bsh[j][d];
            c = fmaf(df, df, c);
        }
        C2row[j] = c * SCALE;
    }
    __syncwarp();
#pragma unroll
    for (int j = 0; j < NPTS; j++) CshT[warp][j][lane] = C2row[j];

    float U = 0.f, V = 0.f;

    for (int t = 0; t < MAX_ITER; t++) {
        vsh[warp][lane] = V;
        __syncwarp();
        float ma = -1e30f, mb = -1e30f;
#pragma unroll
        for (int j4 = 0; j4 < 8; j4 += 2) {
            float4 va = *(const float4*)&vsh[warp][j4 * 4];
            float4 vb = *(const float4*)&vsh[warp][j4 * 4 + 4];
            ma = fmaxf(ma, fmaxf(fmaxf(va.x - C2row[j4 * 4 + 0], va.y - C2row[j4 * 4 + 1]),
                                 fmaxf(va.z - C2row[j4 * 4 + 2], va.w - C2row[j4 * 4 + 3])));
            mb = fmaxf(mb, fmaxf(fmaxf(vb.x - C2row[j4 * 4 + 4], vb.y - C2row[j4 * 4 + 5]),
                                 fmaxf(vb.z - C2row[j4 * 4 + 6], vb.w - C2row[j4 * 4 + 7])));
        }
        float m = fmaxf(ma, mb);
        float sa = 0.f, sb = 0.f;
#pragma unroll
        for (int j4 = 0; j4 < 8; j4 += 2) {
            float4 va = *(const float4*)&vsh[warp][j4 * 4];
            float4 vb = *(const float4*)&vsh[warp][j4 * 4 + 4];
            float e0 = ex2(va.x - C2row[j4 * 4 + 0] - m);
            float e1 = ex2(va.y - C2row[j4 * 4 + 1] - m);
            float e2 = ex2(va.z - C2row[j4 * 4 + 2] - m);
            float e3 = ex2(va.w - C2row[j4 * 4 + 3] - m);
            float f0 = ex2(vb.x - C2row[j4 * 4 + 4] - m);
            float f1 = ex2(vb.y - C2row[j4 * 4 + 5] - m);
            float f2 = ex2(vb.z - C2row[j4 * 4 + 6] - m);
            float f3 = ex2(vb.w - C2row[j4 * 4 + 7] - m);
            sa += (e0 + e1) + (e2 + e3);
            sb += (f0 + f1) + (f2 + f3);
        }
        float Unew = K2LOG - (m + lg2(sa + sb));
        float dU = fabsf(Unew - U);
        U = Unew;
        redsh[warp][0][t][lane] = dU;
        ush[warp][lane] = U;
        __syncwarp();
        float m2a = -1e30f, m2b = -1e30f;
#pragma unroll
        for (int i4 = 0; i4 < 8; i4 += 2) {
            float4 ua = *(const float4*)&ush[warp][i4 * 4];
            float4 ub = *(const float4*)&ush[warp][i4 * 4 + 4];
            float4 ca = *(const float4*)&CshT[warp][lane][i4 * 4];
            float4 cb = *(const float4*)&CshT[warp][lane][i4 * 4 + 4];
            m2a = fmaxf(m2a, fmaxf(fmaxf(ua.x - ca.x, ua.y - ca.y),
                                   fmaxf(ua.z - ca.z, ua.w - ca.w)));
            m2b = fmaxf(m2b, fmaxf(fmaxf(ub.x - cb.x, ub.y - cb.y),
                                   fmaxf(ub.z - cb.z, ub.w - cb.w)));
        }
        float m2 = fmaxf(m2a, m2b);
        float s2a = 0.f, s2b = 0.f, sca = 0.f, scb = 0.f;
#pragma unroll
        for (int i4 = 0; i4 < 8; i4 += 2) {
            float4 ua = *(const float4*)&ush[warp][i4 * 4];
            float4 ub = *(const float4*)&ush[warp][i4 * 4 + 4];
            float4 ca = *(const float4*)&CshT[warp][lane][i4 * 4];
            float4 cb = *(const float4*)&CshT[warp][lane][i4 * 4 + 4];
            float e0 = ex2(ua.x - ca.x - m2);
            float e1 = ex2(ua.y - ca.y - m2);
            float e2 = ex2(ua.z - ca.z - m2);
            float e3 = ex2(ua.w - ca.w - m2);
            float f0 = ex2(ub.x - cb.x - m2);
            float f1 = ex2(ub.y - cb.y - m2);
            float f2 = ex2(ub.z - cb.z - m2);
            float f3 = ex2(ub.w - cb.w - m2);
            s2a += (e0 + e1) + (e2 + e3);
            s2b += (f0 + f1) + (f2 + f3);
            sca += fmaf(e0, ca.x, e1 * ca.y) + fmaf(e2, ca.z, e3 * ca.w);
            scb += fmaf(f0, cb.x, f1 * cb.y) + fmaf(f2, cb.z, f3 * cb.w);
        }
        float s2 = s2a + s2b;
        V = K2LOG - (m2 + lg2(s2));
        redsh[warp][1][t][lane] = NU_TILDE * __fdividef(sca + scb, s2 * SCALE);
    }
    __syncwarp();

    if (lane < 2 * MAX_ITER) {
        const int which = (lane < MAX_ITER) ? 0 : 1;
        const int t = (lane < MAX_ITER) ? lane : lane - MAX_ITER;
        float ssum = 0.f;
#pragma unroll
        for (int i = 0; i < NPTS; i++) ssum += redsh[warp][which][t][i];
        if (which == 0) atomicAdd(&g_err[batch * MAX_ITER + t], ssum);
        else            g_cost[p * MAX_ITER + t] = ssum;
    }
}

// ---------------- reduce: pick iteration T-1 cost, accumulate loss -----------
__global__ __launch_bounds__(256) void sge_reduce(int E)
{
    __shared__ double sd[256];
    __shared__ int Tsh[2];
    if (threadIdx.x < 2) {
        int b = threadIdx.x;
        int T = MAX_ITER;
        float invE = 1.0f / (float)E;
        for (int t = 0; t < MAX_ITER; t++)
            if (g_err[b * MAX_ITER + t] * invE < THRESH_SCALED) { T = t + 1; break; }
        Tsh[b] = T;
    }
    __syncthreads();
    int p = blockIdx.x * 256 + threadIdx.x;
    double con = 0.0;
    if (p < 2 * E) {
        int b = (p >= E) ? 1 : 0;
        float c = g_cost[p * MAX_ITER + Tsh[b] - 1];
        float energy = -c;
        con = b ? (double)__expf(energy) : (double)energy * (double)energy;
    }
    sd[threadIdx.x] = con;
    __syncthreads();
    for (int s2 = 128; s2; s2 >>= 1) {
        if (threadIdx.x < s2) sd[threadIdx.x] += sd[threadIdx.x + s2];
        __syncthreads();
    }
    if (threadIdx.x == 0) atomicAdd(&g_accd, sd[0]);
}

// ---------------- finalize ---------------------------------------------------
__global__ void sge_finalize_kernel(float* out, int out_size, int E)
{
    float loss = (float)(g_accd / (double)E);
    for (int i = threadIdx.x; i < out_size; i += blockDim.x) out[i] = loss;
}

// ---------------- launch -----------------------------------------------------
extern "C" void kernel_launch(void* const* d_in, const int* in_sizes, int n_in,
                              void* d_out, int out_size)
{
    const float* x = (const float*)d_in[0];
    const float* W = (const float*)d_in[1];
    const int* ep  = (const int*)d_in[2];
    const int* en  = (const int*)d_in[3];
    int M = in_sizes[0] / FEAT;
    if (M > MAX_NODES) M = MAX_NODES;
    int E = in_sizes[2] / 2;
    if (E > MAX_E) E = MAX_E;

    static bool attr_set = false;
    if (!attr_set) {
        cudaFuncSetAttribute(sge_gemm_mma,
                             cudaFuncAttributeMaxDynamicSharedMemorySize,
                             2 * STAGE_BYTES);
        attr_set = true;
    }

    sge_convert_x<<<(MPAD * FEAT / 4 + 255) / 256, 256>>>(x, M);
    sge_convert_w<<<dim3(FEAT / 32, EMB / 32), 256>>>(W);
    sge_gemm_mma<<<dim3(EMB / 128, MPAD / 128), 256, 2 * STAGE_BYTES>>>(M);
    int nblocks = (2 * E + PPB - 1) / PPB;
    sge_sinkhorn_pass1<<<nblocks, 128>>>(ep, en, E);
    sge_reduce<<<(2 * E + 255) / 256, 256>>>(E);
    sge_finalize_kernel<<<1, 32>>>((float*)d_out, out_size, E);
}